// round 5
// baseline (speedup 1.0000x reference)
#include <cuda_runtime.h>
#include <cuda_fp16.h>

#define NN 50000
#define EE 800000
#define D  128
#define H  8
#define NBLK 49   // ceil(NN / 1024)

typedef unsigned long long u64;

// Persistent device scratch.
__device__ __half g_h2 [NN * D];   // h = x @ W, fp16 (gather traffic halved)
__device__ float  g_x2 [NN * D];   // layer-2 input (activated layer-1 output)
__device__ float  g_el [NN * H];
__device__ float  g_er [NN * H];
__device__ int    g_deg[NN];       // in-degree histogram (zeroed by gather L2)
__device__ int    g_off[NN];       // exclusive prefix (CSR row offsets)
__device__ int    g_pos[NN];       // running write cursor for scatter
__device__ int    g_ssrc[EE];      // src ids sorted by dst
__device__ int    g_bsum[NBLK];    // scan block sums

// ---- packed f32x2 helpers (Blackwell FFMA2) ----
__device__ __forceinline__ u64 fma2(u64 a, u64 b, u64 c) {
    u64 d;
    asm("fma.rn.f32x2 %0, %1, %2, %3;" : "=l"(d) : "l"(a), "l"(b), "l"(c));
    return d;
}
__device__ __forceinline__ u64 pack2(float lo, float hi) {
    u64 d;
    asm("mov.b64 %0, {%1, %2};" : "=l"(d) : "f"(lo), "f"(hi));
    return d;
}
__device__ __forceinline__ void unpack2(float& lo, float& hi, u64 v) {
    asm("mov.b64 {%0, %1}, %2;" : "=f"(lo), "=f"(hi) : "l"(v));
}

// ---------------------------------------------------------------------------
// CSR build (per launch; graph shared by both layers).
// g_deg arrives zeroed: module-load zeros on first call, gather-L2 re-zeroes
// on every call thereafter.
// ---------------------------------------------------------------------------
__global__ __launch_bounds__(256) void k_count(const int* __restrict__ dst)
{
    int e = blockIdx.x * 256 + threadIdx.x;
    if (e < EE) atomicAdd(&g_deg[dst[e]], 1);
}

__global__ __launch_bounds__(1024) void k_scan1()
{
    __shared__ int wsum[32];
    int i = blockIdx.x * 1024 + threadIdx.x;
    int v = (i < NN) ? g_deg[i] : 0;
    int lane = threadIdx.x & 31, w = threadIdx.x >> 5;
    int x = v;
    #pragma unroll
    for (int o = 1; o < 32; o <<= 1) {
        int t = __shfl_up_sync(0xffffffffu, x, o);
        if (lane >= o) x += t;
    }
    if (lane == 31) wsum[w] = x;
    __syncthreads();
    if (w == 0) {
        int s = wsum[lane];
        #pragma unroll
        for (int o = 1; o < 32; o <<= 1) {
            int t = __shfl_up_sync(0xffffffffu, s, o);
            if (lane >= o) s += t;
        }
        wsum[lane] = s;
    }
    __syncthreads();
    int excl = x - v + (w > 0 ? wsum[w - 1] : 0);
    if (i < NN) g_off[i] = excl;
    if (threadIdx.x == 1023) g_bsum[blockIdx.x] = wsum[31];
}

__global__ __launch_bounds__(64) void k_scan2()
{
    __shared__ int w0sum;
    int t = threadIdx.x, lane = t & 31, w = t >> 5;
    int v = (t < NBLK) ? g_bsum[t] : 0;
    int x = v;
    #pragma unroll
    for (int o = 1; o < 32; o <<= 1) {
        int s = __shfl_up_sync(0xffffffffu, x, o);
        if (lane >= o) x += s;
    }
    if (w == 0 && lane == 31) w0sum = x;
    __syncthreads();
    int excl = x - v + (w ? w0sum : 0);
    if (t < NBLK) g_bsum[t] = excl;
}

__global__ __launch_bounds__(1024) void k_scan3()
{
    int i = blockIdx.x * 1024 + threadIdx.x;
    if (i < NN) {
        int o = g_off[i] + g_bsum[blockIdx.x];
        g_off[i] = o;
        g_pos[i] = o;
    }
}

__global__ __launch_bounds__(256) void k_scatter(const int* __restrict__ src,
                                                const int* __restrict__ dst)
{
    int e = blockIdx.x * 256 + threadIdx.x;
    if (e < EE) {
        int p = atomicAdd(&g_pos[dst[e]], 1);
        g_ssrc[p] = src[e];
    }
}

// ---------------------------------------------------------------------------
// GEMM + attention-coefficient kernel. Per-warp 8 nodes x 128 cols, packed
// fma.rn.f32x2 math. el/er computed from exact fp32 accumulators; h stored
// as fp16 (halves gather + store traffic).
// ---------------------------------------------------------------------------
__global__ __launch_bounds__(128) void gat_gemm(
    const float* __restrict__ xin, const float* __restrict__ W,
    const float* __restrict__ al,  const float* __restrict__ ar, int layer)
{
    __shared__ float xs[4 * 8 * D];   // 16 KB

    const float* x = (layer == 0) ? xin : g_x2;

    int tid  = threadIdx.x;
    int warp = tid >> 5;
    int lane = tid & 31;
    int head = lane >> 2;
    int sub  = lane & 3;

    float4 alv = *(const float4*)(al + head * 16 + sub * 4);
    float4 arv = *(const float4*)(ar + head * 16 + sub * 4);

    const float4* W4 = (const float4*)W;
    float* xw = xs + warp * 8 * D;

    for (int base = (blockIdx.x * 4 + warp) * 8; base < NN;
         base += gridDim.x * 4 * 8)
    {
        #pragma unroll
        for (int i = 0; i < 8; i++)
            ((float4*)(xw + i * D))[lane] =
                ((const float4*)(x + (size_t)(base + i) * D))[lane];
        __syncwarp();

        u64 a0[8], a1[8];
        #pragma unroll
        for (int i = 0; i < 8; i++) { a0[i] = 0ull; a1[i] = 0ull; }

        for (int k0 = 0; k0 < D; k0 += 4) {
            float4 w0 = __ldg(W4 + (k0 + 0) * (D / 4) + lane);
            float4 w1 = __ldg(W4 + (k0 + 1) * (D / 4) + lane);
            float4 w2 = __ldg(W4 + (k0 + 2) * (D / 4) + lane);
            float4 w3 = __ldg(W4 + (k0 + 3) * (D / 4) + lane);
            u64 wl0 = pack2(w0.x, w0.y), wh0 = pack2(w0.z, w0.w);
            u64 wl1 = pack2(w1.x, w1.y), wh1 = pack2(w1.z, w1.w);
            u64 wl2 = pack2(w2.x, w2.y), wh2 = pack2(w2.z, w2.w);
            u64 wl3 = pack2(w3.x, w3.y), wh3 = pack2(w3.z, w3.w);

            #pragma unroll
            for (int i = 0; i < 8; i++) {
                float4 xv = *(const float4*)(xw + i * D + k0);
                u64 xx;
                xx = pack2(xv.x, xv.x);
                a0[i] = fma2(xx, wl0, a0[i]); a1[i] = fma2(xx, wh0, a1[i]);
                xx = pack2(xv.y, xv.y);
                a0[i] = fma2(xx, wl1, a0[i]); a1[i] = fma2(xx, wh1, a1[i]);
                xx = pack2(xv.z, xv.z);
                a0[i] = fma2(xx, wl2, a0[i]); a1[i] = fma2(xx, wh2, a1[i]);
                xx = pack2(xv.w, xv.w);
                a0[i] = fma2(xx, wl3, a0[i]); a1[i] = fma2(xx, wh3, a1[i]);
            }
        }

        #pragma unroll
        for (int i = 0; i < 8; i++) {
            int n = base + i;
            float c0, c1, c2, c3;
            unpack2(c0, c1, a0[i]);
            unpack2(c2, c3, a1[i]);

            __half2 p01 = __floats2half2_rn(c0, c1);
            __half2 p23 = __floats2half2_rn(c2, c3);
            uint2 st;
            st.x = *(unsigned*)&p01;
            st.y = *(unsigned*)&p23;
            ((uint2*)(g_h2 + (size_t)n * D))[lane] = st;

            float pel = c0 * alv.x + c1 * alv.y + c2 * alv.z + c3 * alv.w;
            float per = c0 * arv.x + c1 * arv.y + c2 * arv.z + c3 * arv.w;
            pel += __shfl_xor_sync(0xffffffffu, pel, 1);
            pel += __shfl_xor_sync(0xffffffffu, pel, 2);
            per += __shfl_xor_sync(0xffffffffu, per, 1);
            per += __shfl_xor_sync(0xffffffffu, per, 2);
            if (sub == 0) {
                g_el[n * H + head] = pel;
                g_er[n * H + head] = per;
            }
        }
        __syncwarp();
    }
}

// ---------------------------------------------------------------------------
// Gather-aggregate: one warp per destination node; fp16 h rows (256 B/edge),
// fp32 weights/accumulators; softmax division + activation + store fused.
// Layer 2 additionally re-zeroes g_deg for the next graph replay.
// ---------------------------------------------------------------------------
__global__ __launch_bounds__(256) void gat_gather(float* __restrict__ out,
                                                  int layer)
{
    int n = blockIdx.x * 8 + (threadIdx.x >> 5);
    if (n >= NN) return;
    int lane = threadIdx.x & 31;
    int head = lane >> 2;

    int start = g_off[n];
    int deg   = g_deg[n];
    if (layer == 1 && lane == 0) g_deg[n] = 0;   // restore invariant
    float er_d = __ldg(g_er + n * H + head);

    float4 acc = make_float4(0.f, 0.f, 0.f, 0.f);
    float  z   = 0.f;

    #pragma unroll 4
    for (int j = 0; j < deg; j++) {
        int s = __ldg(g_ssrc + start + j);   // uniform across warp
        float e = __ldg(g_el + s * H + head) + er_d;
        e = e > 0.f ? e : 0.2f * e;
        float a = __expf(e);
        z += a;
        uint2 rv = *(const uint2*)(g_h2 + (size_t)s * D + lane * 4);
        __half2 h01 = *(__half2*)&rv.x;
        __half2 h23 = *(__half2*)&rv.y;
        float2 f01 = __half22float2(h01);
        float2 f23 = __half22float2(h23);
        acc.x = fmaf(a, f01.x, acc.x);
        acc.y = fmaf(a, f01.y, acc.y);
        acc.z = fmaf(a, f23.x, acc.z);
        acc.w = fmaf(a, f23.y, acc.w);
    }

    float inv = (z > 0.f) ? 1.f / z : 0.f;
    float4 v = make_float4(acc.x * inv, acc.y * inv, acc.z * inv, acc.w * inv);

    if (layer == 0) {
        v.x = v.x > 0.f ? v.x : 0.01f * v.x;
        v.y = v.y > 0.f ? v.y : 0.01f * v.y;
        v.z = v.z > 0.f ? v.z : 0.01f * v.z;
        v.w = v.w > 0.f ? v.w : 0.01f * v.w;
        *(float4*)(g_x2 + (size_t)n * D + lane * 4) = v;
    } else {
        *(float4*)(out + (size_t)n * D + lane * 4) = v;
    }
}

// ---------------------------------------------------------------------------
extern "C" void kernel_launch(void* const* d_in, const int* in_sizes, int n_in,
                              void* d_out, int out_size)
{
    const float* n_feat = (const float*)d_in[0];
    const int*   src    = (const int*)  d_in[1];
    const int*   dst    = (const int*)  d_in[2];
    const float* W1     = (const float*)d_in[3];
    const float* al1    = (const float*)d_in[4];
    const float* ar1    = (const float*)d_in[5];
    const float* W2     = (const float*)d_in[6];
    const float* al2    = (const float*)d_in[7];
    const float* ar2    = (const float*)d_in[8];
    float* out = (float*)d_out;

    const int gemm_grid = (NN + 31) / 32;
    const int gath_grid = (NN + 7) / 8;

    // CSR build (g_deg already zeroed by previous call's gather L2)
    k_count  <<<(EE + 255) / 256, 256>>>(dst);
    k_scan1  <<<NBLK, 1024>>>();
    k_scan2  <<<1, 64>>>();
    k_scan3  <<<NBLK, 1024>>>();
    k_scatter<<<(EE + 255) / 256, 256>>>(src, dst);

    // Layer 1
    gat_gemm  <<<gemm_grid, 128>>>(n_feat, W1, al1, ar1, 0);
    gat_gather<<<gath_grid, 256>>>(out, 0);   // writes g_x2 (+act)

    // Layer 2
    gat_gemm  <<<gemm_grid, 128>>>(n_feat, W2, al2, ar2, 1);
    gat_gather<<<gath_grid, 256>>>(out, 1);   // writes d_out, zeroes g_deg
}